// round 9
// baseline (speedup 1.0000x reference)
#include <cuda_runtime.h>
#include <cstdint>

// ---------------------------------------------------------------------------
// BiRNN (bidirectional masked LSTM), B=64, S=1024, D=512, U=512.
// Persistent kernel: 128 blocks (64/dir), each block owns 8 units (32 gate
// cols) with its [1024,32] fp32 weight slice resident in shared memory.
// Inner product uses packed fma.rn.f32x2 (FFMA2) -> 2x fp32 MAC rate.
// One software grid barrier per direction per timestep.
// ---------------------------------------------------------------------------

namespace {
constexpr int Bk = 64;
constexpr int Sk = 1024;
constexpr int Dk = 512;
constexpr int Uk = 512;
constexpr int KT = 1024;          // D + U
constexpr int THREADS = 256;
constexpr int NBLK_DIR = 64;
constexpr int CH = 128;           // k-chunk
constexpr int NCH = KT / CH;      // 8
constexpr int XROW = CH + 4;      // 132 floats per staged row (16B-aligned, conflict-free)

// shared-memory layout (in floats)
constexpr int SW_OFF  = 0;                        // [1024][32] = 32768
constexpr int SX0_OFF = 32768;                    // [64][132]  =  8448
constexpr int SX1_OFF = SX0_OFF + Bk * XROW;      // 41216
constexpr int ZB_OFF  = SX1_OFF + Bk * XROW;      // 49664 : [64][36] = 2304
constexpr int SC_OFF  = ZB_OFF + Bk * 36;         // 51968 : [64][8]  = 512
constexpr int SL_OFF  = SC_OFF + Bk * 8;          // 52480 : lengths (int)
constexpr int SMEM_FLOATS = SL_OFF + Bk;          // 52544
constexpr int SMEM_BYTES  = SMEM_FLOATS * 4;      // 210176 B (< 228 KB)
}

// persistent device state (re-initialized by init_kernel every launch)
__device__ __align__(16) float g_h[2][2][Bk][Uk];  // [dir][phase][b][u]
__device__ int      g_len[Bk];
__device__ unsigned g_bar[2];

// ---------------------------------------------------------------------------
// init: zero h ping-pong buffers, reset barriers, recover lengths[] from the
// mask buffer robustly across serializations (1-byte bool vs 4-byte word).
// ---------------------------------------------------------------------------
__global__ void birnn_init_kernel(const void* __restrict__ maskraw) {
    const int tid = threadIdx.x;  // 256 threads, 1 block
    float* hz = &g_h[0][0][0][0];
    for (int i = tid; i < 2 * 2 * Bk * Uk; i += 256) hz[i] = 0.0f;
    if (tid < 2) g_bar[tid] = 0u;
    if (tid < Bk) {
        const unsigned char* m8 = (const unsigned char*)maskraw;
        int cnt8 = 0;
        bool bytes_ok = true;
        for (int s = 0; s < Sk; ++s) {
            unsigned char v = m8[tid * Sk + s];
            if (v > 1) bytes_ok = false;
            cnt8 += (v != 0);
        }
        bool ok8 = bytes_ok && (cnt8 >= Sk / 2);
        if (ok8) {   // verify prefix structure
            if (m8[tid * Sk + cnt8 - 1] == 0) ok8 = false;
            else if (cnt8 < Sk && m8[tid * Sk + cnt8] != 0) ok8 = false;
        }
        int len;
        if (ok8) {
            len = cnt8;
        } else {
            const unsigned* m32 = (const unsigned*)maskraw;
            int c = 0;
            for (int s = 0; s < Sk; ++s) c += (m32[tid * Sk + s] != 0u);
            len = c;
        }
        g_len[tid] = len;
    }
}

// ---------------------------------------------------------------------------
// packed f32x2 helpers (FFMA2 — PTX-only on sm_103a)
// ---------------------------------------------------------------------------
__device__ __forceinline__ unsigned long long pk2(float v) {
    unsigned long long r;
    asm("mov.b64 %0, {%1, %1};" : "=l"(r) : "f"(v));
    return r;
}
__device__ __forceinline__ unsigned long long pkf2(float lo, float hi) {
    unsigned long long r;
    asm("mov.b64 %0, {%1, %2};" : "=l"(r) : "f"(lo), "f"(hi));
    return r;
}
__device__ __forceinline__ void ffma2(unsigned long long& a,
                                      unsigned long long x,
                                      unsigned long long w) {
    asm("fma.rn.f32x2 %0, %1, %2, %0;" : "+l"(a) : "l"(x), "l"(w));
}
__device__ __forceinline__ float2 up2(unsigned long long a) {
    float2 f;
    asm("mov.b64 {%0, %1}, %2;" : "=f"(f.x), "=f"(f.y) : "l"(a));
    return f;
}

__device__ __forceinline__ float sigf(float x) {
    return 1.0f / (1.0f + __expf(-x));
}

// ---------------------------------------------------------------------------
// main persistent kernel
// ---------------------------------------------------------------------------
extern __shared__ float smem[];

__global__ void __launch_bounds__(THREADS, 1)
birnn_kernel(const float* __restrict__ x,
             const float* __restrict__ kern_f, const float* __restrict__ rkern_f,
             const float* __restrict__ bias_f,
             const float* __restrict__ kern_b, const float* __restrict__ rkern_b,
             const float* __restrict__ bias_b,
             float* __restrict__ out) {
    const int tid  = threadIdx.x;
    const int dir  = blockIdx.x >> 6;        // 0 = fwd, 1 = bwd
    const int blk  = blockIdx.x & 63;        // block within direction
    const int ubase = blk * 8;               // 8 units per block

    const float* kern  = dir ? kern_b  : kern_f;
    const float* rkern = dir ? rkern_b : rkern_f;
    const float* bias  = dir ? bias_b  : bias_f;

    float* sW  = smem + SW_OFF;              // [k][32] (global k)
    float* sXa = smem + SX0_OFF;             // [64][132]
    float* sXb = smem + SX1_OFF;
    float* zb  = smem + ZB_OFF;              // [64][36]
    float* sC  = smem + SC_OFF;              // [64][8]
    int*   sLenI = (int*)(smem + SL_OFF);

    // ---- one-time preload: weight slice [1024][32] ----
    // col c in [0,32): gate g = c>>3, local unit ul = c&7
    for (int i = tid; i < KT * 32; i += THREADS) {
        int k = i >> 5, c = i & 31;
        int gcol = ((c >> 3) << 9) + ubase + (c & 7);     // g*512 + ubase + ul
        float v = (k < Dk) ? kern[k * 2048 + gcol]
                           : rkern[(k - Dk) * 2048 + gcol];
        sW[i] = v;
    }
    for (int i = tid; i < Bk * 8; i += THREADS) sC[i] = 0.0f;
    if (tid < Bk) sLenI[tid] = g_len[tid];

    // thread tile: 2 batches (bg + 32m) x 4 cols (4*cg .. +3)
    const int cg = tid & 7;
    const int bg = tid >> 3;                 // 0..31
    const int c0 = 4 * cg;
    const int gcol0 = ((c0 >> 3) << 9) + ubase + (c0 & 7);
    const float4 biasv = *(const float4*)&bias[gcol0];
    const unsigned long long bias01 = pkf2(biasv.x, biasv.y);
    const unsigned long long bias23 = pkf2(biasv.z, biasv.w);

    __syncthreads();

    uint32_t smem_u32 = (uint32_t)__cvta_generic_to_shared(smem);
    uint32_t sx_u32[2] = { smem_u32 + (uint32_t)SX0_OFF * 4u,
                           smem_u32 + (uint32_t)SX1_OFF * 4u };

    const float* hdirbase = &g_h[dir][0][0][0];  // [phase][b][u]

    // stage one 128-k chunk of [x_t || h_t] into an sX buffer (async, L2-only)
    auto issue = [&](int ci, int bufsel, int s_idx, int rp) {
        const int k0 = ci * CH;
        const float* hbase = hdirbase + (size_t)rp * Bk * Uk;
        #pragma unroll
        for (int i = tid; i < Bk * (CH / 4); i += THREADS) {  // 64 b x 32 float4
            int b = i >> 5, q = i & 31;
            int k = k0 + 4 * q;
            const float* src = (k < Dk)
                ? (x + ((size_t)b * Sk + s_idx) * Dk + k)
                : (hbase + b * Uk + (k - Dk));
            uint32_t dst = sx_u32[bufsel] + (uint32_t)((b * XROW + 4 * q) * 4);
            asm volatile("cp.async.cg.shared.global [%0], [%1], 16;\n"
                         :: "r"(dst), "l"(src));
        }
        asm volatile("cp.async.commit_group;\n");
    };

    // prologue: chunk 0 of step 0 (pure x, no h dependency)
    issue(0, 0, dir ? (Sk - 1) : 0, 0);

    for (int t = 0; t < Sk; ++t) {
        const int rp = t & 1;
        const int wp = rp ^ 1;
        const int sidx = dir ? (Sk - 1 - t) : t;

        unsigned long long acc[2][2];
        acc[0][0] = bias01; acc[0][1] = bias23;
        acc[1][0] = bias01; acc[1][1] = bias23;

        for (int ci = 0; ci < NCH; ++ci) {
            if (ci < NCH - 1) {
                issue(ci + 1, (ci + 1) & 1, sidx, rp);
                asm volatile("cp.async.wait_group 1;\n" ::: "memory");
            } else {
                asm volatile("cp.async.wait_group 0;\n" ::: "memory");
            }
            __syncthreads();   // chunk ci visible to all threads

            const float* Xc = (ci & 1) ? sXb : sXa;
            const float* Wk = sW + ci * CH * 32;

            #pragma unroll 8
            for (int kk = 0; kk < CH; kk += 4) {
                ulonglong2 w0 = *(const ulonglong2*)&Wk[(kk + 0) * 32 + c0];
                ulonglong2 w1 = *(const ulonglong2*)&Wk[(kk + 1) * 32 + c0];
                ulonglong2 w2 = *(const ulonglong2*)&Wk[(kk + 2) * 32 + c0];
                ulonglong2 w3 = *(const ulonglong2*)&Wk[(kk + 3) * 32 + c0];
                #pragma unroll
                for (int m = 0; m < 2; ++m) {
                    float4 xv = *(const float4*)&Xc[(bg + 32 * m) * XROW + kk];
                    unsigned long long p;
                    p = pk2(xv.x);
                    ffma2(acc[m][0], p, w0.x); ffma2(acc[m][1], p, w0.y);
                    p = pk2(xv.y);
                    ffma2(acc[m][0], p, w1.x); ffma2(acc[m][1], p, w1.y);
                    p = pk2(xv.z);
                    ffma2(acc[m][0], p, w2.x); ffma2(acc[m][1], p, w2.y);
                    p = pk2(xv.w);
                    ffma2(acc[m][0], p, w3.x); ffma2(acc[m][1], p, w3.y);
                }
            }
            __syncthreads();   // protect buffer reuse before next issue
        }

        // prefetch chunk 0 of next step (pure x, safe before the barrier)
        if (t + 1 < Sk) issue(0, 0, dir ? (Sk - 2 - t) : (t + 1), wp);

        // ---- epilogue: gates, mask, state update ----
        #pragma unroll
        for (int m = 0; m < 2; ++m) {
            float2 a0 = up2(acc[m][0]);
            float2 a1 = up2(acc[m][1]);
            float4 v = make_float4(a0.x, a0.y, a1.x, a1.y);
            *(float4*)&zb[(bg + 32 * m) * 36 + c0] = v;
        }
        __syncthreads();

        #pragma unroll
        for (int r = 0; r < 2; ++r) {
            int id = tid + r * THREADS;      // 512 tasks: (b, ul)
            int ul = id & 7, b = id >> 3;
            int ug = ubase + ul;
            float zi = zb[b * 36 + ul];
            float zf = zb[b * 36 + 8 + ul];
            float zg = zb[b * 36 + 16 + ul];
            float zo = zb[b * 36 + 24 + ul];
            float cold = sC[b * 8 + ul];
            float cn = sigf(zf) * cold + sigf(zi) * tanhf(zg);
            float hn = sigf(zo) * tanhf(cn);
            bool act = sidx < sLenI[b];
            float co = act ? cn : cold;
            float ho;
            if (act) ho = hn;
            else     ho = __ldcg(&g_h[dir][rp][b][ug]);   // carry previous h
            sC[b * 8 + ul] = co;
            __stcg(&g_h[dir][wp][b][ug], ho);
            out[((size_t)b * Sk + sidx) * (2 * Uk) + dir * Uk + ug] = ho;
        }

        __threadfence();
        __syncthreads();

        // ---- per-direction grid barrier ----
        if (tid == 0) {
            const unsigned target = (unsigned)(t + 1) * (unsigned)NBLK_DIR;
            atomicAdd(&g_bar[dir], 1u);
            volatile unsigned* p = &g_bar[dir];
            while (*p < target) { }
        }
        __syncthreads();
    }

    // ---- final states: h_f, c_f, h_b, c_b ----
    const int fin = Sk & 1;   // final write phase
    const size_t obase = (size_t)Bk * Sk * (2 * Uk);
    #pragma unroll
    for (int r = 0; r < 2; ++r) {
        int id = tid + r * THREADS;
        int ul = id & 7, b = id >> 3;
        int ug = ubase + ul;
        float hf = __ldcg(&g_h[dir][fin][b][ug]);
        float cf = sC[b * 8 + ul];
        size_t doff = obase + (size_t)dir * 2 * Bk * Uk;
        out[doff + (size_t)b * Uk + ug] = hf;                       // h
        out[doff + (size_t)Bk * Uk + (size_t)b * Uk + ug] = cf;     // c
    }
}

// ---------------------------------------------------------------------------
extern "C" void kernel_launch(void* const* d_in, const int* in_sizes, int n_in,
                              void* d_out, int out_size) {
    const float* x     = (const float*)d_in[0];
    const void*  mask  = d_in[1];
    const float* kf    = (const float*)d_in[2];
    const float* rkf   = (const float*)d_in[3];
    const float* bf    = (const float*)d_in[4];
    const float* kb    = (const float*)d_in[5];
    const float* rkb   = (const float*)d_in[6];
    const float* bb    = (const float*)d_in[7];
    float* out = (float*)d_out;

    cudaFuncSetAttribute(birnn_kernel,
                         cudaFuncAttributeMaxDynamicSharedMemorySize, SMEM_BYTES);

    birnn_init_kernel<<<1, 256>>>(mask);
    birnn_kernel<<<2 * NBLK_DIR, THREADS, SMEM_BYTES>>>(
        x, kf, rkf, bf, kb, rkb, bb, out);
}

// round 11
// speedup vs baseline: 1.9176x; 1.9176x over previous
#include <cuda_runtime.h>
#include <cuda_bf16.h>
#include <cstdint>

// ---------------------------------------------------------------------------
// BiRNN (bidirectional masked LSTM), B=64, S=1024, D=U=512.
// mma.sync (HMMA, base sm_103 PTX) version with bf16 limb-split (3 products)
// for fp32-grade accuracy. 128 persistent blocks (64/dir), each owns 8 units
// (N=32 gate cols). A (x||h) and B (weights) stored PRE-PERMUTED in exact
// mma-fragment register order -> plain LDS.128, no ldmatrix, no swizzle.
// ---------------------------------------------------------------------------

namespace {
constexpr int Bk = 64;
constexpr int Sk = 1024;
constexpr int Dk = 512;
constexpr int Uk = 512;
constexpr int THREADS  = 256;           // 8 warps: wr = wid&3 (M16), nh = wid>>2 (N16)
constexpr int NBLK_DIR = 64;
constexpr int NCH      = 8;             // K chunks of 128 (8 k16-steps each)
constexpr uint32_t CHUNK_B = 32768;     // 8 ks x 2 limb x 4 wr x 32 thr x 16B
constexpr uint32_t XSTEP_B = 4 * CHUNK_B;  // x part (k 0..511) per timestep

// smem byte offsets
constexpr uint32_t SB   = 0;                    // W frags: 64ks x2limb x2nh x32 x16B = 128KB
constexpr uint32_t SA0  = 131072;               // A chunk buf0: 32KB
constexpr uint32_t SA1  = 163840;               // A chunk buf1: 32KB
constexpr uint32_t SZ   = 196608;               // zS [64][34] f32 = 8704
constexpr uint32_t SHH  = SZ + 64 * 34 * 4;     // 205312: sH [64][9] f32
constexpr uint32_t SCC  = SHH + 64 * 9 * 4;     // 207616: sC [64][9] f32
constexpr uint32_t SBI  = SCC + 64 * 9 * 4;     // 209920: bias [32] f32
constexpr uint32_t SLEN = SBI + 128;            // 210048: lengths [64] int
constexpr uint32_t SMEM_BYTES = SLEN + 256;     // 210304 (< 227KB)
}

// persistent device state
__device__ __align__(16) unsigned char g_xA[(size_t)Sk * XSTEP_B];   // 128 MB
__device__ __align__(16) unsigned char g_hA[2][2][XSTEP_B];          // [dir][phase]
__device__ int      g_len[Bk];
__device__ unsigned g_bar[2];

// ---------------------------------------------------------------------------
// init: zero h buffers + barriers, recover lengths[] (proven logic)
// ---------------------------------------------------------------------------
__global__ void birnn_init_kernel(const void* __restrict__ maskraw) {
    const int tid = threadIdx.x;  // 256 threads, 1 block
    unsigned* hz = (unsigned*)&g_hA[0][0][0];
    for (int i = tid; i < (int)(2 * 2 * XSTEP_B / 4); i += 256) hz[i] = 0u;
    if (tid < 2) g_bar[tid] = 0u;
    if (tid < Bk) {
        const unsigned char* m8 = (const unsigned char*)maskraw;
        int cnt8 = 0;
        bool bytes_ok = true;
        for (int s = 0; s < Sk; ++s) {
            unsigned char v = m8[tid * Sk + s];
            if (v > 1) bytes_ok = false;
            cnt8 += (v != 0);
        }
        bool ok8 = bytes_ok && (cnt8 >= Sk / 2);
        if (ok8) {
            if (m8[tid * Sk + cnt8 - 1] == 0) ok8 = false;
            else if (cnt8 < Sk && m8[tid * Sk + cnt8] != 0) ok8 = false;
        }
        int len;
        if (ok8) len = cnt8;
        else {
            const unsigned* m32 = (const unsigned*)maskraw;
            int c = 0;
            for (int s = 0; s < Sk; ++s) c += (m32[tid * Sk + s] != 0u);
            len = c;
        }
        g_len[tid] = len;
    }
}

// ---------------------------------------------------------------------------
// bf16 limb helpers
// ---------------------------------------------------------------------------
__device__ __forceinline__ unsigned short bf16hi(float v) {
    __nv_bfloat16 h = __float2bfloat16(v);
    return *(unsigned short*)&h;
}
__device__ __forceinline__ unsigned short bf16lo(float v) {
    __nv_bfloat16 h = __float2bfloat16(v);
    float r = v - __bfloat162float(h);
    __nv_bfloat16 l = __float2bfloat16(r);
    return *(unsigned short*)&l;
}

// ---------------------------------------------------------------------------
// x pre-conversion: fp32 -> bf16 limb fragments in mma register layout.
// Slot (ci, ks, limb, wr, t) holds 16B = regs j0..j3; reg j covers
//   row = wr*16 + (t>>2) + 8*(j&1),  k = (ci*8+ks)*16 + (t&3)*2 + 8*(j>>1), k+1
// ---------------------------------------------------------------------------
__global__ void birnn_xconv_kernel(const float* __restrict__ x) {
    const int s = blockIdx.x;
    const int tid = threadIdx.x;   // 256
    unsigned char* dst_base = g_xA + (size_t)s * XSTEP_B;
    for (int sl = tid; sl < 8192; sl += 256) {
        int t    = sl & 31;
        int wr   = (sl >> 5) & 3;
        int limb = (sl >> 7) & 1;
        int ks   = (sl >> 8) & 7;
        int ci   = sl >> 11;
        uint4 pk;
        unsigned* pq = (unsigned*)&pk;
        #pragma unroll
        for (int j = 0; j < 4; ++j) {
            int row = wr * 16 + (t >> 2) + 8 * (j & 1);
            int k   = (ci * 8 + ks) * 16 + (t & 3) * 2 + 8 * (j >> 1);
            float2 v = *(const float2*)&x[((size_t)row * Sk + s) * Dk + k];
            unsigned short u0 = limb ? bf16lo(v.x) : bf16hi(v.x);
            unsigned short u1 = limb ? bf16lo(v.y) : bf16hi(v.y);
            pq[j] = (unsigned)u0 | ((unsigned)u1 << 16);
        }
        *(uint4*)(dst_base + (size_t)ci * CHUNK_B
                  + (uint32_t)((((ks * 2 + limb) * 4 + wr) * 32 + t) * 16)) = pk;
    }
}

// ---------------------------------------------------------------------------
__device__ __forceinline__ void mma16816(float* c, uint4 a,
                                         uint32_t b0, uint32_t b1) {
    asm volatile(
        "mma.sync.aligned.m16n8k16.row.col.f32.bf16.bf16.f32 "
        "{%0,%1,%2,%3}, {%4,%5,%6,%7}, {%8,%9}, {%0,%1,%2,%3};"
        : "+f"(c[0]), "+f"(c[1]), "+f"(c[2]), "+f"(c[3])
        : "r"(a.x), "r"(a.y), "r"(a.z), "r"(a.w), "r"(b0), "r"(b1));
}

__device__ __forceinline__ float sigf(float x) {
    return 1.0f / (1.0f + __expf(-x));
}

// ---------------------------------------------------------------------------
// main persistent kernel: 128 blocks (64/dir), 256 threads
// ---------------------------------------------------------------------------
extern __shared__ __align__(16) unsigned char smraw[];

__global__ void __launch_bounds__(THREADS, 1)
birnn_kernel(const float* __restrict__ kern_f, const float* __restrict__ rkern_f,
             const float* __restrict__ bias_f,
             const float* __restrict__ kern_b, const float* __restrict__ rkern_b,
             const float* __restrict__ bias_b,
             float* __restrict__ out) {
    const int tid = threadIdx.x;
    const int wid = tid >> 5;
    const int lid = tid & 31;
    const int wr  = wid & 3;        // M row group (16 rows)
    const int nh  = wid >> 2;       // N half (cols 16*nh..16*nh+15)
    const int dir = blockIdx.x >> 6;
    const int blk = blockIdx.x & 63;
    const int ubase = blk * 8;      // 8 units per block (N=32 gate cols)

    const float* kern  = dir ? kern_b  : kern_f;
    const float* rkern = dir ? rkern_b : rkern_f;
    const float* bias  = dir ? bias_b  : bias_f;

    uint32_t smem_u32 = (uint32_t)__cvta_generic_to_shared(smraw);
    float* zS    = (float*)(smraw + SZ);      // [64][34]
    float* sH    = (float*)(smraw + SHH);     // [64][9]
    float* sC    = (float*)(smraw + SCC);     // [64][9]
    float* biasS = (float*)(smraw + SBI);     // [32]
    int*   sLen  = (int*)(smraw + SLEN);

    // ---- one-time: build W fragments (bf16 limbs) in register layout ----
    // Slot (ks 0..63, limb, nhs 0..1, t): 16B = [nf0.b0, nf0.b1, nf1.b0, nf1.b1]
    // reg q: nf = 2*nhs + (q>>1), k = ks*16 + (t&3)*2 + (q&1)*8 (+1),
    //        col = nf*8 + (t>>2)
    for (int sl = tid; sl < 8192; sl += THREADS) {
        int t    = sl & 31;
        int nhs  = (sl >> 5) & 1;
        int limb = (sl >> 6) & 1;
        int ks   = sl >> 7;
        uint4 pk;
        unsigned* pq = (unsigned*)&pk;
        #pragma unroll
        for (int q = 0; q < 4; ++q) {
            int nf  = 2 * nhs + (q >> 1);
            int k   = ks * 16 + (t & 3) * 2 + (q & 1) * 8;
            int col = nf * 8 + (t >> 2);
            int gcol = ((col >> 3) << 9) + ubase + (col & 7);
            float v0 = (k < Dk)     ? kern[k * 2048 + gcol]
                                    : rkern[(k - Dk) * 2048 + gcol];
            float v1 = (k + 1 < Dk) ? kern[(k + 1) * 2048 + gcol]
                                    : rkern[(k + 1 - Dk) * 2048 + gcol];
            unsigned short u0 = limb ? bf16lo(v0) : bf16hi(v0);
            unsigned short u1 = limb ? bf16lo(v1) : bf16hi(v1);
            pq[q] = (unsigned)u0 | ((unsigned)u1 << 16);
        }
        *(uint4*)(smraw + SB + (uint32_t)((((ks * 2 + limb) * 2 + nhs) * 32 + t) * 16)) = pk;
    }
    if (tid < 32) {
        int gcol = ((tid >> 3) << 9) + ubase + (tid & 7);
        biasS[tid] = bias[gcol];
    }
    for (int i = tid; i < Bk * 9; i += THREADS) { sH[i] = 0.0f; sC[i] = 0.0f; }
    if (tid < Bk) sLen[tid] = g_len[tid];
    __syncthreads();

    // stage one 32KB A chunk (raw copy: global layout == smem layout)
    auto stage = [&](int ci, int buf, int sidx, int rp) {
        const unsigned char* src = (ci < 4)
            ? (g_xA + (size_t)sidx * XSTEP_B + (uint32_t)ci * CHUNK_B)
            : (&g_hA[dir][rp][0] + (uint32_t)(ci - 4) * CHUNK_B);
        uint32_t dst = smem_u32 + (buf ? SA1 : SA0);
        #pragma unroll
        for (int j = 0; j < 8; ++j) {   // 2048 x 16B / 256 threads
            uint32_t off = (uint32_t)(j * 256 + tid) * 16;
            asm volatile("cp.async.cg.shared.global [%0], [%1], 16;\n"
                         :: "r"(dst + off), "l"(src + off));
        }
        asm volatile("cp.async.commit_group;\n");
    };

    // prologue: chunk 0 of step 0 (pure x)
    stage(0, 0, dir ? (Sk - 1) : 0, 0);

    for (int t = 0; t < Sk; ++t) {
        const int rp = t & 1, wp = rp ^ 1;
        const int sidx = dir ? (Sk - 1 - t) : t;

        float acc0[2][4], acc1[2][4];
        #pragma unroll
        for (int f = 0; f < 2; ++f)
            #pragma unroll
            for (int i = 0; i < 4; ++i) { acc0[f][i] = 0.0f; acc1[f][i] = 0.0f; }

        for (int ci = 0; ci < NCH; ++ci) {
            const int buf = ci & 1;
            if (ci < NCH - 1) {
                stage(ci + 1, buf ^ 1, sidx, rp);
                asm volatile("cp.async.wait_group 1;\n" ::: "memory");
            } else {
                asm volatile("cp.async.wait_group 0;\n" ::: "memory");
            }
            __syncthreads();

            const unsigned char* sa = smraw + (buf ? SA1 : SA0);
            #pragma unroll
            for (int ks = 0; ks < 8; ++ks) {
                const int ksg = ci * 8 + ks;
                uint4 ahi = *(const uint4*)(sa +
                    (uint32_t)((((ks * 2 + 0) * 4 + wr) * 32 + lid) * 16));
                uint4 alo = *(const uint4*)(sa +
                    (uint32_t)((((ks * 2 + 1) * 4 + wr) * 32 + lid) * 16));
                uint4 bhi = *(const uint4*)(smraw + SB +
                    (uint32_t)((((ksg * 2 + 0) * 2 + nh) * 32 + lid) * 16));
                uint4 blo = *(const uint4*)(smraw + SB +
                    (uint32_t)((((ksg * 2 + 1) * 2 + nh) * 32 + lid) * 16));
                mma16816(acc0[0], ahi, bhi.x, bhi.y);
                mma16816(acc0[1], ahi, bhi.z, bhi.w);
                mma16816(acc1[0], ahi, blo.x, blo.y);
                mma16816(acc1[1], ahi, blo.z, blo.w);
                mma16816(acc1[0], alo, bhi.x, bhi.y);
                mma16816(acc1[1], alo, bhi.z, bhi.w);
            }
            __syncthreads();   // protect buffer before next stage overwrites
        }

        // prefetch chunk0 of next step (pure x; buf0 free after chunk6)
        if (t + 1 < Sk) stage(0, 0, dir ? (Sk - 2 - t) : (t + 1), wp);

        // ---- accumulators -> zS ----
        #pragma unroll
        for (int f = 0; f < 2; ++f) {
            float c0 = acc0[f][0] + acc1[f][0];
            float c1 = acc0[f][1] + acc1[f][1];
            float c2 = acc0[f][2] + acc1[f][2];
            float c3 = acc0[f][3] + acc1[f][3];
            int row = wr * 16 + (lid >> 2);
            int col = (2 * nh + f) * 8 + (lid & 3) * 2;
            *(float2*)&zS[row * 34 + col]       = make_float2(c0, c1);
            *(float2*)&zS[(row + 8) * 34 + col] = make_float2(c2, c3);
        }
        __syncthreads();

        // ---- gates, mask, state update (512 tasks) ----
        #pragma unroll
        for (int r = 0; r < 2; ++r) {
            int id = tid + r * THREADS;
            int ul = id & 7, b = id >> 3;
            int ug = ubase + ul;
            float zi = zS[b * 34 + ul]      + biasS[ul];
            float zf = zS[b * 34 + 8 + ul]  + biasS[8 + ul];
            float zg = zS[b * 34 + 16 + ul] + biasS[16 + ul];
            float zo = zS[b * 34 + 24 + ul] + biasS[24 + ul];
            float cold = sC[b * 9 + ul];
            float cn = sigf(zf) * cold + sigf(zi) * tanhf(zg);
            float hn = sigf(zo) * tanhf(cn);
            bool act = sidx < sLen[b];
            float co = act ? cn : cold;
            float ho = act ? hn : sH[b * 9 + ul];
            sC[b * 9 + ul] = co;
            sH[b * 9 + ul] = ho;
            out[((size_t)b * Sk + sidx) * (2 * Uk) + dir * Uk + ug] = ho;
        }
        __syncthreads();

        // ---- publish h limbs into fragment layout for all blocks ----
        // Block's 8 units -> k = 512 + 8*blk + ul; chunk = blk>>4,
        // ks = (blk>>1)&7, k-half j-offset = 2*(blk&1).
        {
            unsigned char* hb = &g_hA[dir][wp][0] + (uint32_t)(blk >> 4) * CHUNK_B;
            const int ks_h = (blk >> 1) & 7;
            #pragma unroll
            for (int r = 0; r < 2; ++r) {
                int id = tid + r * THREADS;        // 512 tasks: (p, limb, b)
                int p = id & 3, limb = (id >> 2) & 1, b = id >> 3;
                float v0 = sH[b * 9 + 2 * p];
                float v1 = sH[b * 9 + 2 * p + 1];
                unsigned short u0 = limb ? bf16lo(v0) : bf16hi(v0);
                unsigned short u1 = limb ? bf16lo(v1) : bf16hi(v1);
                unsigned val = (unsigned)u0 | ((unsigned)u1 << 16);
                int tslot = (b & 7) * 4 + p;
                int j = ((b >> 3) & 1) + 2 * (blk & 1);
                unsigned* dst = (unsigned*)(hb +
                    (uint32_t)((((ks_h * 2 + limb) * 4 + (b >> 4)) * 32 + tslot) * 16
                               + j * 4));
                __stcg(dst, val);
            }
        }
        __threadfence();
        __syncthreads();

        // ---- per-direction grid barrier ----
        if (tid == 0) {
            const unsigned target = (unsigned)(t + 1) * (unsigned)NBLK_DIR;
            atomicAdd(&g_bar[dir], 1u);
            volatile unsigned* p = &g_bar[dir];
            while (*p < target) { }
        }
        __syncthreads();
    }

    // ---- final states: h_f, c_f, h_b, c_b ----
    const size_t obase = (size_t)Bk * Sk * (2 * Uk);
    #pragma unroll
    for (int r = 0; r < 2; ++r) {
        int id = tid + r * THREADS;
        int ul = id & 7, b = id >> 3;
        int ug = ubase + ul;
        size_t doff = obase + (size_t)dir * 2 * Bk * Uk;
        out[doff + (size_t)b * Uk + ug] = sH[b * 9 + ul];
        out[doff + (size_t)Bk * Uk + (size_t)b * Uk + ug] = sC[b * 9 + ul];
    }
}

// ---------------------------------------------------------------------------
extern "C" void kernel_launch(void* const* d_in, const int* in_sizes, int n_in,
                              void* d_out, int out_size) {
    const float* x    = (const float*)d_in[0];
    const void*  mask = d_in[1];
    const float* kf   = (const float*)d_in[2];
    const float* rkf  = (const float*)d_in[3];
    const float* bf   = (const float*)d_in[4];
    const float* kb   = (const float*)d_in[5];
    const float* rkb  = (const float*)d_in[6];
    const float* bb   = (const float*)d_in[7];
    float* out = (float*)d_out;

    cudaFuncSetAttribute(birnn_kernel,
                         cudaFuncAttributeMaxDynamicSharedMemorySize, SMEM_BYTES);

    birnn_init_kernel<<<1, 256>>>(mask);
    birnn_xconv_kernel<<<Sk, 256>>>(x);
    birnn_kernel<<<2 * NBLK_DIR, THREADS, SMEM_BYTES>>>(
        kf, rkf, bf, kb, rkb, bb, out);
}

// round 12
// speedup vs baseline: 2.1192x; 1.1051x over previous
#include <cuda_runtime.h>
#include <cuda_bf16.h>
#include <cstdint>

// ---------------------------------------------------------------------------
// BiRNN (bidirectional masked LSTM), B=64, S=1024, D=U=512.
// mma.sync (HMMA) with bf16 limb-split (3 products) for fp32-grade accuracy.
// 128 persistent blocks (64/dir), each owns 8 units (N=32 gate cols).
// A (x||h) and B (weights) stored PRE-PERMUTED in mma-fragment register
// order -> plain LDS.128. This round: barrier overlapped with the x-half of
// the GEMM, release/acquire grid barrier, out-stores off the critical path,
// parallel init.
// ---------------------------------------------------------------------------

namespace {
constexpr int Bk = 64;
constexpr int Sk = 1024;
constexpr int Dk = 512;
constexpr int Uk = 512;
constexpr int THREADS  = 256;           // 8 warps: wr = wid&3 (M16), nh = wid>>2 (N16)
constexpr int NBLK_DIR = 64;
constexpr uint32_t CHUNK_B = 32768;     // 8 ks x 2 limb x 4 wr x 32 thr x 16B
constexpr uint32_t XSTEP_B = 4 * CHUNK_B;  // x part (k 0..511) per timestep

// smem byte offsets
constexpr uint32_t SB   = 0;                    // W frags: 64ks x2limb x2nh x32 x16B = 128KB
constexpr uint32_t SA0  = 131072;               // A chunk buf0: 32KB
constexpr uint32_t SA1  = 163840;               // A chunk buf1: 32KB
constexpr uint32_t SZ   = 196608;               // zS [64][34] f32 = 8704
constexpr uint32_t SHH  = SZ + 64 * 34 * 4;     // 205312: sH [64][9] f32
constexpr uint32_t SCC  = SHH + 64 * 9 * 4;     // 207616: sC [64][9] f32
constexpr uint32_t SBI  = SCC + 64 * 9 * 4;     // 209920: bias [32] f32
constexpr uint32_t SLEN = SBI + 128;            // 210048: lengths [64] int
constexpr uint32_t SMEM_BYTES = SLEN + 256;     // 210304 (< 227KB)
}

// persistent device state
__device__ __align__(16) unsigned char g_xA[(size_t)Sk * XSTEP_B];   // 128 MB
__device__ __align__(16) unsigned char g_hA[2][2][XSTEP_B];          // [dir][phase]
__device__ int      g_len[Bk];
__device__ unsigned g_bar[2];

// ---------------------------------------------------------------------------
// init (grid 64): zero h buffers + barriers, recover lengths[] in parallel.
// Semantics identical to the proven serial version.
// ---------------------------------------------------------------------------
__global__ void birnn_init_kernel(const void* __restrict__ maskraw) {
    const int b = blockIdx.x;       // 64 blocks, 256 threads
    const int tid = threadIdx.x;
    // zero slice of g_hA (524288 B total / 64 blocks = 512 uint4)
    uint4* hz = (uint4*)&g_hA[0][0][0];
    hz[b * 512 + tid]       = make_uint4(0, 0, 0, 0);
    hz[b * 512 + 256 + tid] = make_uint4(0, 0, 0, 0);
    if (b == 0 && tid < 2) g_bar[tid] = 0u;

    __shared__ int s_cnt8, s_bad8, s_cnt32;
    if (tid == 0) { s_cnt8 = 0; s_bad8 = 0; s_cnt32 = 0; }
    __syncthreads();
    // byte hypothesis: row = 1024 bytes
    if (tid < 64) {
        const uchar4* m = (const uchar4*)((const unsigned char*)maskraw + b * 1024);
        int c = 0, bad = 0;
        #pragma unroll
        for (int j = 0; j < 4; ++j) {
            uchar4 v = m[tid * 4 + j];
            c   += (v.x != 0) + (v.y != 0) + (v.z != 0) + (v.w != 0);
            bad += (v.x > 1)  + (v.y > 1)  + (v.z > 1)  + (v.w > 1);
        }
        atomicAdd(&s_cnt8, c);
        if (bad) atomicAdd(&s_bad8, 1);
    }
    // word hypothesis: row = 1024 words
    {
        const uint4* m = (const uint4*)((const unsigned*)maskraw + b * 1024);
        uint4 v = m[tid];
        int c = (v.x != 0u) + (v.y != 0u) + (v.z != 0u) + (v.w != 0u);
        atomicAdd(&s_cnt32, c);
    }
    __syncthreads();
    if (tid == 0) {
        const unsigned char* m8 = (const unsigned char*)maskraw + b * 1024;
        int cnt8 = s_cnt8;
        bool ok8 = (s_bad8 == 0) && (cnt8 >= Sk / 2);
        if (ok8) {
            if (m8[cnt8 - 1] == 0) ok8 = false;
            else if (cnt8 < Sk && m8[cnt8] != 0) ok8 = false;
        }
        g_len[b] = ok8 ? cnt8 : s_cnt32;
    }
}

// ---------------------------------------------------------------------------
// bf16 limb helpers
// ---------------------------------------------------------------------------
__device__ __forceinline__ unsigned short bf16hi(float v) {
    __nv_bfloat16 h = __float2bfloat16(v);
    return *(unsigned short*)&h;
}
__device__ __forceinline__ unsigned short bf16lo(float v) {
    __nv_bfloat16 h = __float2bfloat16(v);
    float r = v - __bfloat162float(h);
    __nv_bfloat16 l = __float2bfloat16(r);
    return *(unsigned short*)&l;
}

// ---------------------------------------------------------------------------
// x pre-conversion: fp32 -> bf16 limb fragments in mma register layout.
// Slot (ci, ks, limb, wr, t) holds 16B = regs j0..j3; reg j covers
//   row = wr*16 + (t>>2) + 8*(j&1),  k = (ci*8+ks)*16 + (t&3)*2 + 8*(j>>1), k+1
// ---------------------------------------------------------------------------
__global__ void birnn_xconv_kernel(const float* __restrict__ x) {
    const int s = blockIdx.x;
    const int tid = threadIdx.x;   // 256
    unsigned char* dst_base = g_xA + (size_t)s * XSTEP_B;
    for (int sl = tid; sl < 8192; sl += 256) {
        int t    = sl & 31;
        int wr   = (sl >> 5) & 3;
        int limb = (sl >> 7) & 1;
        int ks   = (sl >> 8) & 7;
        int ci   = sl >> 11;
        uint4 pk;
        unsigned* pq = (unsigned*)&pk;
        #pragma unroll
        for (int j = 0; j < 4; ++j) {
            int row = wr * 16 + (t >> 2) + 8 * (j & 1);
            int k   = (ci * 8 + ks) * 16 + (t & 3) * 2 + 8 * (j >> 1);
            float2 v = *(const float2*)&x[((size_t)row * Sk + s) * Dk + k];
            unsigned short u0 = limb ? bf16lo(v.x) : bf16hi(v.x);
            unsigned short u1 = limb ? bf16lo(v.y) : bf16hi(v.y);
            pq[j] = (unsigned)u0 | ((unsigned)u1 << 16);
        }
        *(uint4*)(dst_base + (size_t)ci * CHUNK_B
                  + (uint32_t)((((ks * 2 + limb) * 4 + wr) * 32 + t) * 16)) = pk;
    }
}

// ---------------------------------------------------------------------------
__device__ __forceinline__ void mma16816(float* c, uint4 a,
                                         uint32_t b0, uint32_t b1) {
    asm volatile(
        "mma.sync.aligned.m16n8k16.row.col.f32.bf16.bf16.f32 "
        "{%0,%1,%2,%3}, {%4,%5,%6,%7}, {%8,%9}, {%0,%1,%2,%3};"
        : "+f"(c[0]), "+f"(c[1]), "+f"(c[2]), "+f"(c[3])
        : "r"(a.x), "r"(a.y), "r"(a.z), "r"(a.w), "r"(b0), "r"(b1));
}

__device__ __forceinline__ float sigf(float x) {
    return 1.0f / (1.0f + __expf(-x));
}

__device__ __forceinline__ void bar_arrive(unsigned* p) {
    asm volatile("red.release.gpu.global.add.u32 [%0], 1;" :: "l"(p) : "memory");
}
__device__ __forceinline__ void bar_wait(unsigned* p, unsigned target) {
    unsigned v;
    do {
        asm volatile("ld.acquire.gpu.global.u32 %0, [%1];"
                     : "=r"(v) : "l"(p) : "memory");
    } while (v < target);
}

// ---------------------------------------------------------------------------
// main persistent kernel: 128 blocks (64/dir), 256 threads
// ---------------------------------------------------------------------------
extern __shared__ __align__(16) unsigned char smraw[];

__global__ void __launch_bounds__(THREADS, 1)
birnn_kernel(const float* __restrict__ kern_f, const float* __restrict__ rkern_f,
             const float* __restrict__ bias_f,
             const float* __restrict__ kern_b, const float* __restrict__ rkern_b,
             const float* __restrict__ bias_b,
             float* __restrict__ out) {
    const int tid = threadIdx.x;
    const int wid = tid >> 5;
    const int lid = tid & 31;
    const int wr  = wid & 3;        // M row group (16 rows)
    const int nh  = wid >> 2;       // N half (cols 16*nh..16*nh+15)
    const int dir = blockIdx.x >> 6;
    const int blk = blockIdx.x & 63;
    const int ubase = blk * 8;      // 8 units per block (N=32 gate cols)

    const float* kern  = dir ? kern_b  : kern_f;
    const float* rkern = dir ? rkern_b : rkern_f;
    const float* bias  = dir ? bias_b  : bias_f;

    uint32_t smem_u32 = (uint32_t)__cvta_generic_to_shared(smraw);
    float* zS    = (float*)(smraw + SZ);      // [64][34]
    float* sH    = (float*)(smraw + SHH);     // [64][9]
    float* sC    = (float*)(smraw + SCC);     // [64][9]
    float* biasS = (float*)(smraw + SBI);     // [32]
    int*   sLen  = (int*)(smraw + SLEN);

    // ---- one-time: build W fragments (bf16 limbs) in register layout ----
    for (int sl = tid; sl < 8192; sl += THREADS) {
        int t    = sl & 31;
        int nhs  = (sl >> 5) & 1;
        int limb = (sl >> 6) & 1;
        int ks   = sl >> 7;
        uint4 pk;
        unsigned* pq = (unsigned*)&pk;
        #pragma unroll
        for (int q = 0; q < 4; ++q) {
            int nf  = 2 * nhs + (q >> 1);
            int k   = ks * 16 + (t & 3) * 2 + (q & 1) * 8;
            int col = nf * 8 + (t >> 2);
            int gcol = ((col >> 3) << 9) + ubase + (col & 7);
            float v0 = (k < Dk)     ? kern[k * 2048 + gcol]
                                    : rkern[(k - Dk) * 2048 + gcol];
            float v1 = (k + 1 < Dk) ? kern[(k + 1) * 2048 + gcol]
                                    : rkern[(k + 1 - Dk) * 2048 + gcol];
            unsigned short u0 = limb ? bf16lo(v0) : bf16hi(v0);
            unsigned short u1 = limb ? bf16lo(v1) : bf16hi(v1);
            pq[q] = (unsigned)u0 | ((unsigned)u1 << 16);
        }
        *(uint4*)(smraw + SB + (uint32_t)((((ks * 2 + limb) * 2 + nhs) * 32 + t) * 16)) = pk;
    }
    if (tid < 32) {
        int gcol = ((tid >> 3) << 9) + ubase + (tid & 7);
        biasS[tid] = bias[gcol];
    }
    for (int i = tid; i < Bk * 9; i += THREADS) { sH[i] = 0.0f; sC[i] = 0.0f; }
    if (tid < Bk) sLen[tid] = g_len[tid];
    __syncthreads();

    // stage one 32KB A chunk (raw copy: global layout == smem layout)
    auto stage = [&](int ci, int sidx, int rp) {
        const unsigned char* src = (ci < 4)
            ? (g_xA + (size_t)sidx * XSTEP_B + (uint32_t)ci * CHUNK_B)
            : (&g_hA[dir][rp][0] + (uint32_t)(ci - 4) * CHUNK_B);
        uint32_t dst = smem_u32 + ((ci & 1) ? SA1 : SA0);
        #pragma unroll
        for (int j = 0; j < 8; ++j) {   // 2048 x 16B / 256 threads
            uint32_t off = (uint32_t)(j * 256 + tid) * 16;
            asm volatile("cp.async.cg.shared.global [%0], [%1], 16;\n"
                         :: "r"(dst + off), "l"(src + off));
        }
        asm volatile("cp.async.commit_group;\n");
    };

    float acc0[2][4], acc1[2][4];

    auto mma_chunk = [&](int ci) {
        const unsigned char* sa = smraw + ((ci & 1) ? SA1 : SA0);
        #pragma unroll
        for (int ks = 0; ks < 8; ++ks) {
            const int ksg = ci * 8 + ks;
            uint4 ahi = *(const uint4*)(sa +
                (uint32_t)((((ks * 2 + 0) * 4 + wr) * 32 + lid) * 16));
            uint4 alo = *(const uint4*)(sa +
                (uint32_t)((((ks * 2 + 1) * 4 + wr) * 32 + lid) * 16));
            uint4 bhi = *(const uint4*)(smraw + SB +
                (uint32_t)((((ksg * 2 + 0) * 2 + nh) * 32 + lid) * 16));
            uint4 blo = *(const uint4*)(smraw + SB +
                (uint32_t)((((ksg * 2 + 1) * 2 + nh) * 32 + lid) * 16));
            mma16816(acc0[0], ahi, bhi.x, bhi.y);
            mma16816(acc0[1], ahi, bhi.z, bhi.w);
            mma16816(acc1[0], ahi, blo.x, blo.y);
            mma16816(acc1[1], ahi, blo.z, blo.w);
            mma16816(acc1[0], alo, bhi.x, bhi.y);
            mma16816(acc1[1], alo, bhi.z, bhi.w);
        }
    };

    // prologue: stage chunks 0,1 of step 0 (pure x)
    stage(0, dir ? (Sk - 1) : 0, 0);
    stage(1, dir ? (Sk - 1) : 0, 0);

    for (int t = 0; t < Sk; ++t) {
        const int rp = t & 1, wp = rp ^ 1;
        const int sidx = dir ? (Sk - 1 - t) : t;

        #pragma unroll
        for (int f = 0; f < 2; ++f)
            #pragma unroll
            for (int i = 0; i < 4; ++i) { acc0[f][i] = 0.0f; acc1[f][i] = 0.0f; }

        // ---- x phase: chunks 0..2 (no h dependency) ----
        #pragma unroll 1
        for (int ci = 0; ci < 3; ++ci) {
            asm volatile("cp.async.wait_group 1;\n" ::: "memory");
            __syncthreads();
            mma_chunk(ci);
            __syncthreads();
            if (ci < 2) stage(ci + 2, sidx, rp);   // chunks 2,3
        }
        asm volatile("cp.async.wait_group 0;\n" ::: "memory");
        __syncthreads();                            // chunk 3 staged & visible

        // ---- grid barrier: h(t-1) published by all blocks ----
        if (tid == 0) bar_wait(&g_bar[dir], (unsigned)t * (unsigned)NBLK_DIR);
        __syncthreads();

        // ---- h phase: chunks 4..7 (chunk-4 latency hidden by mma(3)) ----
        stage(4, sidx, rp);
        mma_chunk(3);
        __syncthreads();
        stage(5, sidx, rp);
        #pragma unroll 1
        for (int ci = 4; ci < 7; ++ci) {
            asm volatile("cp.async.wait_group 1;\n" ::: "memory");
            __syncthreads();
            mma_chunk(ci);
            __syncthreads();
            if (ci < 6) stage(ci + 2, sidx, rp);   // chunks 6,7
        }
        asm volatile("cp.async.wait_group 0;\n" ::: "memory");
        __syncthreads();
        mma_chunk(7);

        // ---- accumulators -> zS ----
        #pragma unroll
        for (int f = 0; f < 2; ++f) {
            float c0 = acc0[f][0] + acc1[f][0];
            float c1 = acc0[f][1] + acc1[f][1];
            float c2 = acc0[f][2] + acc1[f][2];
            float c3 = acc0[f][3] + acc1[f][3];
            int row = wr * 16 + (lid >> 2);
            int col = (2 * nh + f) * 8 + (lid & 3) * 2;
            *(float2*)&zS[row * 34 + col]       = make_float2(c0, c1);
            *(float2*)&zS[(row + 8) * 34 + col] = make_float2(c2, c3);
        }
        __syncthreads();

        // ---- gates, mask, state update (512 tasks) ----
        #pragma unroll
        for (int r = 0; r < 2; ++r) {
            int id = tid + r * THREADS;
            int ul = id & 7, b = id >> 3;
            float zi = zS[b * 34 + ul]      + biasS[ul];
            float zf = zS[b * 34 + 8 + ul]  + biasS[8 + ul];
            float zg = zS[b * 34 + 16 + ul] + biasS[16 + ul];
            float zo = zS[b * 34 + 24 + ul] + biasS[24 + ul];
            float cold = sC[b * 9 + ul];
            float cn = sigf(zf) * cold + sigf(zi) * tanhf(zg);
            float hn = sigf(zo) * tanhf(cn);
            bool act = sidx < sLen[b];
            sC[b * 9 + ul] = act ? cn : cold;
            sH[b * 9 + ul] = act ? hn : sH[b * 9 + ul];
        }
        __syncthreads();

        // ---- publish h limbs into fragment layout for all blocks ----
        {
            unsigned char* hb = &g_hA[dir][wp][0] + (uint32_t)(blk >> 4) * CHUNK_B;
            const int ks_h = (blk >> 1) & 7;
            #pragma unroll
            for (int r = 0; r < 2; ++r) {
                int id = tid + r * THREADS;        // 512 tasks: (p, limb, b)
                int p = id & 3, limb = (id >> 2) & 1, b = id >> 3;
                float v0 = sH[b * 9 + 2 * p];
                float v1 = sH[b * 9 + 2 * p + 1];
                unsigned short u0 = limb ? bf16lo(v0) : bf16hi(v0);
                unsigned short u1 = limb ? bf16lo(v1) : bf16hi(v1);
                unsigned val = (unsigned)u0 | ((unsigned)u1 << 16);
                int tslot = (b & 7) * 4 + p;
                int j = ((b >> 3) & 1) + 2 * (blk & 1);
                unsigned* dst = (unsigned*)(hb +
                    (uint32_t)((((ks_h * 2 + limb) * 4 + (b >> 4)) * 32 + tslot) * 16
                               + j * 4));
                __stcg(dst, val);
            }
        }
        __syncthreads();

        // ---- arrive (release publishes the stcg writes above) ----
        if (tid == 0) bar_arrive(&g_bar[dir]);

        // ---- off-critical-path: out stores + next-step x prefetch ----
        #pragma unroll
        for (int r = 0; r < 2; ++r) {
            int id = tid + r * THREADS;
            int ul = id & 7, b = id >> 3;
            out[((size_t)b * Sk + sidx) * (2 * Uk) + dir * Uk + ubase + ul]
                = sH[b * 9 + ul];
        }
        if (t + 1 < Sk) {
            const int nsidx = dir ? (Sk - 2 - t) : (t + 1);
            stage(0, nsidx, wp);
            stage(1, nsidx, wp);
        }
    }

    // ---- final states: h_f, c_f, h_b, c_b ----
    const size_t obase = (size_t)Bk * Sk * (2 * Uk);
    #pragma unroll
    for (int r = 0; r < 2; ++r) {
        int id = tid + r * THREADS;
        int ul = id & 7, b = id >> 3;
        int ug = ubase + ul;
        size_t doff = obase + (size_t)dir * 2 * Bk * Uk;
        out[doff + (size_t)b * Uk + ug] = sH[b * 9 + ul];
        out[doff + (size_t)Bk * Uk + (size_t)b * Uk + ug] = sC[b * 9 + ul];
    }
}

// ---------------------------------------------------------------------------
extern "C" void kernel_launch(void* const* d_in, const int* in_sizes, int n_in,
                              void* d_out, int out_size) {
    const float* x    = (const float*)d_in[0];
    const void*  mask = d_in[1];
    const float* kf   = (const float*)d_in[2];
    const float* rkf  = (const float*)d_in[3];
    const float* bf   = (const float*)d_in[4];
    const float* kb   = (const float*)d_in[5];
    const float* rkb  = (const float*)d_in[6];
    const float* bb   = (const float*)d_in[7];
    float* out = (float*)d_out;

    cudaFuncSetAttribute(birnn_kernel,
                         cudaFuncAttributeMaxDynamicSharedMemorySize, SMEM_BYTES);

    birnn_init_kernel<<<64, 256>>>(mask);
    birnn_xconv_kernel<<<Sk, 256>>>(x);
    birnn_kernel<<<2 * NBLK_DIR, THREADS, SMEM_BYTES>>>(
        kf, rkf, bf, kb, rkb, bb, out);
}

// round 13
// speedup vs baseline: 2.8560x; 1.3477x over previous
#include <cuda_runtime.h>
#include <cuda_bf16.h>
#include <cstdint>

// ---------------------------------------------------------------------------
// BiRNN (bidirectional masked LSTM), B=64, S=1024, D=U=512.
// Split design:
//   1) birnn_xconv : x -> bf16 limb fragments (mma register layout) in g_xA
//   2) birnn_xgemm : zx = x @ Wx for ALL timesteps (bulk GEMM, 1024 blocks)
//   3) birnn_loop  : sequential recurrence, h-half GEMM only (K=512),
//                    128 persistent blocks (64/dir), grid barrier per step.
// mma.sync m16n8k16 bf16 with limb-split (3 products) -> fp32-grade accuracy.
// ---------------------------------------------------------------------------

namespace {
constexpr int Bk = 64;
constexpr int Sk = 1024;
constexpr int Dk = 512;
constexpr int Uk = 512;
constexpr int THREADS  = 256;          // 8 warps: wr = wid&3 (M16), nh = wid>>2 (N16)
constexpr int NBLK_DIR = 64;
constexpr uint32_t SUB_B   = 16384;    // 16KB sub-chunk = 4 k16-steps
constexpr uint32_t CHUNK32 = 32768;    // xconv 32KB chunk granularity
constexpr uint32_t XSTEP_B = 131072;   // x fragments per timestep (32 ks)

// xgemm smem layout (bytes)
constexpr uint32_t XG_W    = 0;        // W-x frags: 32ks x2limb x2nh x32 x16B = 64KB
constexpr uint32_t XG_A    = 65536;    // ring: 4 x 16KB
constexpr uint32_t XG_SMEM = 131072;

// loop smem layout (bytes)
constexpr uint32_t LP_W    = 0;        // W-h frags: 64KB
constexpr uint32_t LP_A    = 65536;    // ring: 4 x 16KB
constexpr uint32_t LP_ZX   = 131072;   // zx tile [64][40] f32 = 10240
constexpr uint32_t LP_Z    = 141312;   // zS [64][34] f32 = 8704
constexpr uint32_t LP_H    = 150016;   // sH [64][9] f32 = 2304
constexpr uint32_t LP_C    = 152320;   // sC [64][9] f32 = 2304
constexpr uint32_t LP_BI   = 154624;   // bias [32] f32
constexpr uint32_t LP_LEN  = 154752;   // lengths [64] int
constexpr uint32_t LP_SMEM = 155008;
}

// persistent device state
__device__ __align__(16) unsigned char g_xA[(size_t)Sk * XSTEP_B];   // 128 MB
__device__ __align__(16) unsigned char g_hA[2][2][XSTEP_B];          // 512 KB
__device__ float    g_zx[2][NBLK_DIR][Sk][Bk * 32];                  // 1 GB
__device__ int      g_len[Bk];
__device__ unsigned g_bar[2];

// ---------------------------------------------------------------------------
// init (grid 64): zero h buffers + barriers, recover lengths[] in parallel.
// ---------------------------------------------------------------------------
__global__ void birnn_init_kernel(const void* __restrict__ maskraw) {
    const int b = blockIdx.x;       // 64 blocks, 256 threads
    const int tid = threadIdx.x;
    uint4* hz = (uint4*)&g_hA[0][0][0];
    hz[b * 512 + tid]       = make_uint4(0, 0, 0, 0);
    hz[b * 512 + 256 + tid] = make_uint4(0, 0, 0, 0);
    if (b == 0 && tid < 2) g_bar[tid] = 0u;

    __shared__ int s_cnt8, s_bad8, s_cnt32;
    if (tid == 0) { s_cnt8 = 0; s_bad8 = 0; s_cnt32 = 0; }
    __syncthreads();
    if (tid < 64) {
        const uchar4* m = (const uchar4*)((const unsigned char*)maskraw + b * 1024);
        int c = 0, bad = 0;
        #pragma unroll
        for (int j = 0; j < 4; ++j) {
            uchar4 v = m[tid * 4 + j];
            c   += (v.x != 0) + (v.y != 0) + (v.z != 0) + (v.w != 0);
            bad += (v.x > 1)  + (v.y > 1)  + (v.z > 1)  + (v.w > 1);
        }
        atomicAdd(&s_cnt8, c);
        if (bad) atomicAdd(&s_bad8, 1);
    }
    {
        const uint4* m = (const uint4*)((const unsigned*)maskraw + b * 1024);
        uint4 v = m[tid];
        int c = (v.x != 0u) + (v.y != 0u) + (v.z != 0u) + (v.w != 0u);
        atomicAdd(&s_cnt32, c);
    }
    __syncthreads();
    if (tid == 0) {
        const unsigned char* m8 = (const unsigned char*)maskraw + b * 1024;
        int cnt8 = s_cnt8;
        bool ok8 = (s_bad8 == 0) && (cnt8 >= Sk / 2);
        if (ok8) {
            if (m8[cnt8 - 1] == 0) ok8 = false;
            else if (cnt8 < Sk && m8[cnt8] != 0) ok8 = false;
        }
        g_len[b] = ok8 ? cnt8 : s_cnt32;
    }
}

// ---------------------------------------------------------------------------
// bf16 limb helpers
// ---------------------------------------------------------------------------
__device__ __forceinline__ unsigned short bf16hi(float v) {
    __nv_bfloat16 h = __float2bfloat16(v);
    return *(unsigned short*)&h;
}
__device__ __forceinline__ unsigned short bf16lo(float v) {
    __nv_bfloat16 h = __float2bfloat16(v);
    float r = v - __bfloat162float(h);
    __nv_bfloat16 l = __float2bfloat16(r);
    return *(unsigned short*)&l;
}

// ---------------------------------------------------------------------------
// x pre-conversion: fp32 -> bf16 limb fragments in mma register layout.
// ---------------------------------------------------------------------------
__global__ void birnn_xconv_kernel(const float* __restrict__ x) {
    const int s = blockIdx.x;
    const int tid = threadIdx.x;   // 256
    unsigned char* dst_base = g_xA + (size_t)s * XSTEP_B;
    for (int sl = tid; sl < 8192; sl += 256) {
        int t    = sl & 31;
        int wr   = (sl >> 5) & 3;
        int limb = (sl >> 7) & 1;
        int ks   = (sl >> 8) & 7;
        int ci   = sl >> 11;
        uint4 pk;
        unsigned* pq = (unsigned*)&pk;
        #pragma unroll
        for (int j = 0; j < 4; ++j) {
            int row = wr * 16 + (t >> 2) + 8 * (j & 1);
            int k   = (ci * 8 + ks) * 16 + (t & 3) * 2 + 8 * (j >> 1);
            float2 v = *(const float2*)&x[((size_t)row * Sk + s) * Dk + k];
            unsigned short u0 = limb ? bf16lo(v.x) : bf16hi(v.x);
            unsigned short u1 = limb ? bf16lo(v.y) : bf16hi(v.y);
            pq[j] = (unsigned)u0 | ((unsigned)u1 << 16);
        }
        *(uint4*)(dst_base + (size_t)ci * CHUNK32
                  + (uint32_t)((((ks * 2 + limb) * 4 + wr) * 32 + t) * 16)) = pk;
    }
}

// ---------------------------------------------------------------------------
__device__ __forceinline__ void mma16816(float* c, uint4 a,
                                         uint32_t b0, uint32_t b1) {
    asm volatile(
        "mma.sync.aligned.m16n8k16.row.col.f32.bf16.bf16.f32 "
        "{%0,%1,%2,%3}, {%4,%5,%6,%7}, {%8,%9}, {%0,%1,%2,%3};"
        : "+f"(c[0]), "+f"(c[1]), "+f"(c[2]), "+f"(c[3])
        : "r"(a.x), "r"(a.y), "r"(a.z), "r"(a.w), "r"(b0), "r"(b1));
}

// One 16KB A sub-chunk (4 k16-steps) against resident W fragments.
__device__ __forceinline__ void mma_sub(
    const unsigned char* sa, const unsigned char* sw, int ksb,
    int wr, int nh, int lid, float a0[2][4], float a1[2][4]) {
    #pragma unroll
    for (int kl = 0; kl < 4; ++kl) {
        uint4 ahi = *(const uint4*)(sa +
            (uint32_t)((((kl * 2 + 0) * 4 + wr) * 32 + lid) * 16));
        uint4 alo = *(const uint4*)(sa +
            (uint32_t)((((kl * 2 + 1) * 4 + wr) * 32 + lid) * 16));
        int ksg = ksb + kl;
        uint4 bhi = *(const uint4*)(sw +
            (uint32_t)((((ksg * 2 + 0) * 2 + nh) * 32 + lid) * 16));
        uint4 blo = *(const uint4*)(sw +
            (uint32_t)((((ksg * 2 + 1) * 2 + nh) * 32 + lid) * 16));
        mma16816(a0[0], ahi, bhi.x, bhi.y);
        mma16816(a0[1], ahi, bhi.z, bhi.w);
        mma16816(a1[0], ahi, blo.x, blo.y);
        mma16816(a1[1], ahi, blo.z, blo.w);
        mma16816(a1[0], alo, bhi.x, bhi.y);
        mma16816(a1[1], alo, bhi.z, bhi.w);
    }
}

__device__ __forceinline__ float sigf(float x) {
    return 1.0f / (1.0f + __expf(-x));
}
__device__ __forceinline__ void bar_arrive(unsigned* p) {
    asm volatile("red.release.gpu.global.add.u32 [%0], 1;" :: "l"(p) : "memory");
}
__device__ __forceinline__ void bar_wait(unsigned* p, unsigned target) {
    unsigned v;
    do {
        asm volatile("ld.acquire.gpu.global.u32 %0, [%1];"
                     : "=r"(v) : "l"(p) : "memory");
    } while (v < target);
}

// Build W fragments (32 ks, 2 limbs, 2 nh halves) from a k-window.
// wsrc(k_local) must return the fp32 weight row pointer logic via lambda-free
// form: we pass base pointers and an offset flag instead.
template <bool RECURRENT>
__device__ __forceinline__ void build_wfrags(
    unsigned char* sw, const float* w, int ubase, int tid) {
    for (int sl = tid; sl < 4096; sl += THREADS) {
        int t    = sl & 31;
        int nhs  = (sl >> 5) & 1;
        int limb = (sl >> 6) & 1;
        int ks   = sl >> 7;               // 0..31
        uint4 pk;
        unsigned* pq = (unsigned*)&pk;
        #pragma unroll
        for (int q = 0; q < 4; ++q) {
            int nf  = 2 * nhs + (q >> 1);
            int k   = ks * 16 + (t & 3) * 2 + (q & 1) * 8;   // 0..511
            int col = nf * 8 + (t >> 2);
            int gcol = ((col >> 3) << 9) + ubase + (col & 7);
            float v0 = w[(size_t)k * 2048 + gcol];
            float v1 = w[(size_t)(k + 1) * 2048 + gcol];
            unsigned short u0 = limb ? bf16lo(v0) : bf16hi(v0);
            unsigned short u1 = limb ? bf16lo(v1) : bf16hi(v1);
            pq[q] = (unsigned)u0 | ((unsigned)u1 << 16);
        }
        *(uint4*)(sw + (uint32_t)((((ks * 2 + limb) * 2 + nhs) * 32 + t) * 16)) = pk;
    }
}

// ---------------------------------------------------------------------------
// bulk x-GEMM: zx[dir][blk][s][b][32] = x @ Wx   (1024 blocks, no barriers)
// blockIdx.x = dir*512 + blk*8 + stile ; each block: 128 timesteps.
// ---------------------------------------------------------------------------
extern __shared__ __align__(16) unsigned char smraw[];

__global__ void __launch_bounds__(THREADS, 1)
birnn_xgemm_kernel(const float* __restrict__ kern_f,
                   const float* __restrict__ kern_b) {
    const int tid = threadIdx.x;
    const int wid = tid >> 5, lid = tid & 31;
    const int wr = wid & 3, nh = wid >> 2;
    const int bx = blockIdx.x;
    const int dir = bx >> 9;
    const int blk = (bx >> 3) & 63;
    const int s0  = (bx & 7) * 128;
    const int ubase = blk * 8;

    build_wfrags<false>(smraw + XG_W, dir ? kern_b : kern_f, ubase, tid);
    __syncthreads();

    uint32_t smem_u32 = (uint32_t)__cvta_generic_to_shared(smraw);

    auto stage = [&](int it) {
        const unsigned char* src = g_xA
            + (size_t)(s0 + (it >> 3)) * XSTEP_B + (uint32_t)(it & 7) * SUB_B;
        uint32_t dst = smem_u32 + XG_A + (uint32_t)(it & 3) * SUB_B;
        #pragma unroll
        for (int j = 0; j < 4; ++j) {     // 1024 x 16B / 256 threads
            uint32_t off = (uint32_t)(j * 256 + tid) * 16;
            asm volatile("cp.async.cg.shared.global [%0], [%1], 16;\n"
                         :: "r"(dst + off), "l"(src + off));
        }
        asm volatile("cp.async.commit_group;\n");
    };

    stage(0); stage(1); stage(2);

    float a0[2][4], a1[2][4];
    #pragma unroll 1
    for (int it = 0; it < 1024; ++it) {
        const int c = it & 7;
        if (c == 0) {
            #pragma unroll
            for (int f = 0; f < 2; ++f)
                #pragma unroll
                for (int i = 0; i < 4; ++i) { a0[f][i] = 0.0f; a1[f][i] = 0.0f; }
        }
        asm volatile("cp.async.wait_group 2;\n" ::: "memory");
        __syncthreads();
        if (it + 3 < 1024) stage(it + 3);
        else asm volatile("cp.async.commit_group;\n");
        mma_sub(smraw + XG_A + (uint32_t)(it & 3) * SUB_B, smraw + XG_W,
                c * 4, wr, nh, lid, a0, a1);
        if (c == 7) {
            const int sidx = s0 + (it >> 3);
            float* dst = &g_zx[dir][blk][sidx][0];
            #pragma unroll
            for (int f = 0; f < 2; ++f) {
                int row = wr * 16 + (lid >> 2);
                int col = (2 * nh + f) * 8 + (lid & 3) * 2;
                *(float2*)&dst[row * 32 + col] =
                    make_float2(a0[f][0] + a1[f][0], a0[f][1] + a1[f][1]);
                *(float2*)&dst[(row + 8) * 32 + col] =
                    make_float2(a0[f][2] + a1[f][2], a0[f][3] + a1[f][3]);
            }
        }
    }
}

// ---------------------------------------------------------------------------
// recurrent loop: 128 persistent blocks (64/dir), h-half GEMM only.
// ---------------------------------------------------------------------------
__global__ void __launch_bounds__(THREADS, 1)
birnn_loop_kernel(const float* __restrict__ rkern_f,
                  const float* __restrict__ bias_f,
                  const float* __restrict__ rkern_b,
                  const float* __restrict__ bias_b,
                  float* __restrict__ out) {
    const int tid = threadIdx.x;
    const int wid = tid >> 5, lid = tid & 31;
    const int wr = wid & 3, nh = wid >> 2;
    const int dir = blockIdx.x >> 6;
    const int blk = blockIdx.x & 63;
    const int ubase = blk * 8;

    const float* rkern = dir ? rkern_b : rkern_f;
    const float* bias  = dir ? bias_b  : bias_f;

    uint32_t smem_u32 = (uint32_t)__cvta_generic_to_shared(smraw);
    float* zxS   = (float*)(smraw + LP_ZX);   // [64][40]
    float* zS    = (float*)(smraw + LP_Z);    // [64][34]
    float* sH    = (float*)(smraw + LP_H);    // [64][9]
    float* sC    = (float*)(smraw + LP_C);    // [64][9]
    float* biasS = (float*)(smraw + LP_BI);   // [32]
    int*   sLen  = (int*)(smraw + LP_LEN);

    build_wfrags<true>(smraw + LP_W, rkern, ubase, tid);
    if (tid < 32) {
        int gcol = ((tid >> 3) << 9) + ubase + (tid & 7);
        biasS[tid] = bias[gcol];
    }
    for (int i = tid; i < Bk * 9; i += THREADS) { sH[i] = 0.0f; sC[i] = 0.0f; }
    if (tid < Bk) sLen[tid] = g_len[tid];
    __syncthreads();

    auto stage_h = [&](int c, int rp) {
        const unsigned char* src = &g_hA[dir][rp][0] + (uint32_t)c * SUB_B;
        uint32_t dst = smem_u32 + LP_A + (uint32_t)(c & 3) * SUB_B;
        #pragma unroll
        for (int j = 0; j < 4; ++j) {
            uint32_t off = (uint32_t)(j * 256 + tid) * 16;
            asm volatile("cp.async.cg.shared.global [%0], [%1], 16;\n"
                         :: "r"(dst + off), "l"(src + off));
        }
        asm volatile("cp.async.commit_group;\n");
    };
    auto stage_zx = [&](int sidx) {
        const float* src = &g_zx[dir][blk][sidx][0];
        #pragma unroll
        for (int r = 0; r < 2; ++r) {
            int i = tid + r * THREADS;         // 512 x 16B
            int b = i >> 3, p = i & 7;
            uint32_t dst = smem_u32 + LP_ZX + (uint32_t)((b * 40 + p * 4) * 4);
            asm volatile("cp.async.cg.shared.global [%0], [%1], 16;\n"
                         :: "r"(dst), "l"(src + (b * 32 + p * 4)));
        }
        asm volatile("cp.async.commit_group;\n");
    };

    // prologue: zx for step 0
    stage_zx(dir ? (Sk - 1) : 0);

    float a0[2][4], a1[2][4];

    for (int t = 0; t < Sk; ++t) {
        const int rp = t & 1, wp = rp ^ 1;
        const int sidx = dir ? (Sk - 1 - t) : t;

        // wait for h(t-1) publication from all blocks of this direction
        if (tid == 0) bar_wait(&g_bar[dir], (unsigned)t * (unsigned)NBLK_DIR);
        __syncthreads();

        stage_h(0, rp); stage_h(1, rp); stage_h(2, rp);

        #pragma unroll
        for (int f = 0; f < 2; ++f)
            #pragma unroll
            for (int i = 0; i < 4; ++i) { a0[f][i] = 0.0f; a1[f][i] = 0.0f; }

        #pragma unroll 1
        for (int c = 0; c < 8; ++c) {
            asm volatile("cp.async.wait_group 2;\n" ::: "memory");
            __syncthreads();
            if (c < 5) stage_h(c + 3, rp);
            else asm volatile("cp.async.commit_group;\n");
            mma_sub(smraw + LP_A + (uint32_t)(c & 3) * SUB_B, smraw + LP_W,
                    c * 4, wr, nh, lid, a0, a1);
        }

        // ---- accumulators -> zS ----
        #pragma unroll
        for (int f = 0; f < 2; ++f) {
            int row = wr * 16 + (lid >> 2);
            int col = (2 * nh + f) * 8 + (lid & 3) * 2;
            *(float2*)&zS[row * 34 + col] =
                make_float2(a0[f][0] + a1[f][0], a0[f][1] + a1[f][1]);
            *(float2*)&zS[(row + 8) * 34 + col] =
                make_float2(a0[f][2] + a1[f][2], a0[f][3] + a1[f][3]);
        }
        __syncthreads();

        // ---- gates, mask, state update (512 tasks) ----
        #pragma unroll
        for (int r = 0; r < 2; ++r) {
            int id = tid + r * THREADS;
            int ul = id & 7, b = id >> 3;
            float zi = zS[b * 34 + ul]      + zxS[b * 40 + ul]      + biasS[ul];
            float zf = zS[b * 34 + 8 + ul]  + zxS[b * 40 + 8 + ul]  + biasS[8 + ul];
            float zg = zS[b * 34 + 16 + ul] + zxS[b * 40 + 16 + ul] + biasS[16 + ul];
            float zo = zS[b * 34 + 24 + ul] + zxS[b * 40 + 24 + ul] + biasS[24 + ul];
            float cold = sC[b * 9 + ul];
            float cn = sigf(zf) * cold + sigf(zi) * tanhf(zg);
            float hn = sigf(zo) * tanhf(cn);
            bool act = sidx < sLen[b];
            sC[b * 9 + ul] = act ? cn : cold;
            sH[b * 9 + ul] = act ? hn : sH[b * 9 + ul];
        }
        __syncthreads();

        // ---- publish h limbs into fragment layout (flat ks = blk>>1) ----
        {
            unsigned char* hb = &g_hA[dir][wp][0];
            const int ks_h = blk >> 1;
            #pragma unroll
            for (int r = 0; r < 2; ++r) {
                int id = tid + r * THREADS;        // 512 tasks: (p, limb, b)
                int p = id & 3, limb = (id >> 2) & 1, b = id >> 3;
                float v0 = sH[b * 9 + 2 * p];
                float v1 = sH[b * 9 + 2 * p + 1];
                unsigned short u0 = limb ? bf16lo(v0) : bf16hi(v0);
                unsigned short u1 = limb ? bf16lo(v1) : bf16hi(v1);
                unsigned val = (unsigned)u0 | ((unsigned)u1 << 16);
                int tslot = (b & 7) * 4 + p;
                int j = ((b >> 3) & 1) + 2 * (blk & 1);
                unsigned* dst = (unsigned*)(hb +
                    (uint32_t)((((ks_h * 2 + limb) * 4 + (b >> 4)) * 32 + tslot) * 16
                               + j * 4));
                __stcg(dst, val);
            }
        }
        __syncthreads();

        if (tid == 0) bar_arrive(&g_bar[dir]);

        // ---- off critical path: out stores + zx prefetch for t+1 ----
        #pragma unroll
        for (int r = 0; r < 2; ++r) {
            int id = tid + r * THREADS;
            int ul = id & 7, b = id >> 3;
            out[((size_t)b * Sk + sidx) * (2 * Uk) + dir * Uk + ubase + ul]
                = sH[b * 9 + ul];
        }
        if (t + 1 < Sk) stage_zx(dir ? (Sk - 2 - t) : (t + 1));
    }

    // ---- final states: h_f, c_f, h_b, c_b ----
    const size_t obase = (size_t)Bk * Sk * (2 * Uk);
    #pragma unroll
    for (int r = 0; r < 2; ++r) {
        int id = tid + r * THREADS;
        int ul = id & 7, b = id >> 3;
        int ug = ubase + ul;
        size_t doff = obase + (size_t)dir * 2 * Bk * Uk;
        out[doff + (size_t)b * Uk + ug] = sH[b * 9 + ul];
        out[doff + (size_t)Bk * Uk + (size_t)b * Uk + ug] = sC[b * 9 + ul];
    }
}

// ---------------------------------------------------------------------------
extern "C" void kernel_launch(void* const* d_in, const int* in_sizes, int n_in,
                              void* d_out, int out_size) {
    const float* x    = (const float*)d_in[0];
    const void*  mask = d_in[1];
    const float* kf   = (const float*)d_in[2];
    const float* rkf  = (const float*)d_in[3];
    const float* bf   = (const float*)d_in[4];
    const float* kb   = (const float*)d_in[5];
    const float* rkb  = (const float*)d_in[6];
    const float* bb   = (const float*)d_in[7];
    float* out = (float*)d_out;

    cudaFuncSetAttribute(birnn_xgemm_kernel,
                         cudaFuncAttributeMaxDynamicSharedMemorySize, XG_SMEM);
    cudaFuncSetAttribute(birnn_loop_kernel,
                         cudaFuncAttributeMaxDynamicSharedMemorySize, LP_SMEM);

    birnn_init_kernel<<<64, 256>>>(mask);
    birnn_xconv_kernel<<<Sk, 256>>>(x);
    birnn_xgemm_kernel<<<1024, THREADS, XG_SMEM>>>(kf, kb);
    birnn_loop_kernel<<<2 * NBLK_DIR, THREADS, LP_SMEM>>>(
        rkf, bf, rkb, bb, out);
}